// round 16
// baseline (speedup 1.0000x reference)
#include <cuda_runtime.h>
#include <cuda_fp16.h>
#include <cfloat>
#include <math.h>
#include <cstdint>

// Problem shape (fixed by the reference)
#define B_    32
#define N_    4096
#define D_    256
#define K_    1024
#define NROWS (B_ * N_)          // 131072 rows of z_e

#define MARGIN_ 0.001f           // flag threshold (fp16-split fast-path err ~5e-5 => >=10 sigma)

// ---------------------------------------------------------------------------
// SMEM layout (dynamic). Padded strides: row-to-row bank offset = 16B ->
// conflict-free ldmatrix (8 rows span 128B of banks).
// ---------------------------------------------------------------------------
#define A_STRIDE 264                       // 256 + 8 fp16
#define B_STRIDE 72                        // 64 + 8 fp16
#define SM_ESQ   0                         // 1024 f32 = 4 KB
#define SM_AH    4096                      // 128*264*2 = 67584
#define SM_AL    (SM_AH + 67584)
#define SM_B     (SM_AL + 67584)           // 2 stages x (hi 18432 + lo 18432)
#define B_HALF   18432                     // one precision, one stage
#define B_BUFSZ  36864                     // hi+lo per stage
#define SM_RED   (SM_B + 2 * B_BUFSZ)      // 6144: redb/reds/redi
#define SM_RIDX  (SM_RED + 6144)           // 512: final per-row index
#define SM_TOTAL (SM_RIDX + 512)           // 219648 B

// Scratch (static device globals -- no allocation allowed)
__device__ float  g_esq[K_];     // fp32 e_sq for the fast path
__device__ double g_esqd[K_];    // exact e_sq for the fixup
__device__ int    g_idx[NROWS];
__device__ int    g_nflag;
__device__ int    g_flags[NROWS];
// Pre-converted codebook (fp16 hi/lo), tiled EXACTLY like the smem B buffer:
// chunk c (kt=c>>2 codes kt*128..+128, dk=c&3 dims dk*64..+64)
__device__ __align__(16) __half g_cbh[32][128][B_STRIDE];
__device__ __align__(16) __half g_cbl[32][128][B_STRIDE];

__device__ __forceinline__ uint32_t smem_u32(const void* p) {
    uint32_t a;
    asm("{ .reg .u64 t; cvta.to.shared.u64 t, %1; cvt.u32.u64 %0, t; }"
        : "=r"(a) : "l"(p));
    return a;
}

__device__ __forceinline__ void ldmx4(uint32_t* r, uint32_t addr) {
    asm volatile("ldmatrix.sync.aligned.m8n8.x4.shared.b16 {%0,%1,%2,%3}, [%4];"
                 : "=r"(r[0]), "=r"(r[1]), "=r"(r[2]), "=r"(r[3]) : "r"(addr));
}

__device__ __forceinline__ void mma_f16(float* c, const uint32_t* a,
                                        uint32_t b0, uint32_t b1) {
    asm volatile(
        "mma.sync.aligned.m16n8k16.row.col.f32.f16.f16.f32 "
        "{%0,%1,%2,%3}, {%4,%5,%6,%7}, {%8,%9}, {%0,%1,%2,%3};"
        : "+f"(c[0]), "+f"(c[1]), "+f"(c[2]), "+f"(c[3])
        : "r"(a[0]), "r"(a[1]), "r"(a[2]), "r"(a[3]), "r"(b0), "r"(b1));
}

__device__ __forceinline__ uint32_t pack_h2(float x, float y) {
    const __half2 h = __floats2half2_rn(x, y);
    return *(const uint32_t*)&h;
}

__device__ __forceinline__ void cp16(uint32_t saddr, const void* gaddr) {
    asm volatile("cp.async.cg.shared.global [%0], [%1], 16;"
                 :: "r"(saddr), "l"(gaddr) : "memory");
}
#define CP_COMMIT() asm volatile("cp.async.commit_group;" ::: "memory")
#define CP_WAIT0()  asm volatile("cp.async.wait_group 0;" ::: "memory")

// Issue async copy of chunk c into stage buffer `buf`. 2304 x 16B lines
// (hi 1152 + lo 1152), 9 per thread. Zero register residency.
__device__ __forceinline__ void b_issue(uint32_t sbase, int c, int buf, int tid) {
    const uint32_t dhi = sbase + SM_B + (uint32_t)buf * B_BUFSZ;
    const char* shi = (const char*)g_cbh[c];
    const char* slo = (const char*)g_cbl[c];
    #pragma unroll
    for (int it = 0; it < 9; it++) {
        const int line = it * 256 + tid;
        if (line < 1152) {
            cp16(dhi + line * 16, shi + line * 16);
        } else {
            const int l2 = line - 1152;
            cp16(dhi + B_HALF + l2 * 16, slo + l2 * 16);
        }
    }
}

// ---------------------------------------------------------------------------
// Kernel 0: pre-convert codebook into tiled fp16 hi/lo global buffers.
// hi = fp16(x); lo = fp16(x - hi): together ~22 mantissa bits of x.
// ---------------------------------------------------------------------------
__global__ void prep_kernel(const float* __restrict__ cb) {
    const int gid  = blockIdx.x * 256 + threadIdx.x;
    const int c    = gid >> 13;
    const int code = (gid & 8191) >> 6;
    const int d    = gid & 63;
    const int kt = c >> 2, dk = c & 3;
    const float v = cb[(size_t)(kt * 128 + code) * D_ + dk * 64 + d];
    const __half h = __float2half_rn(v);
    const __half l = __float2half_rn(__fsub_rn(v, __half2float(h)));
    g_cbh[c][code][d] = h;
    g_cbl[c][code][d] = l;
}

// ---------------------------------------------------------------------------
// Kernel 1: per-code squared norms, fp32 (fast path) + fp64 (exact, fixup).
// ---------------------------------------------------------------------------
__global__ void esq_kernel(const float* __restrict__ cb) {
    if (blockIdx.x == 0 && threadIdx.x == 0) g_nflag = 0;
    const int k    = blockIdx.x * 8 + (threadIdx.x >> 5);
    const int lane = threadIdx.x & 31;
    const float* row = cb + (size_t)k * D_;
    double sd = 0.0;
    #pragma unroll
    for (int j = 0; j < 8; j++) {
        const double x = (double)row[lane + 32 * j];
        sd = fma(x, x, sd);
    }
    #pragma unroll
    for (int off = 16; off > 0; off >>= 1)
        sd += __shfl_down_sync(0xffffffffu, sd, off);
    if (lane == 0) {
        g_esqd[k] = sd;
        g_esq[k]  = (float)sd;
    }
}

// ---------------------------------------------------------------------------
// Kernel 2: fp16-split warp-MMA GEMM + fused argmin + fused gather.
// dot ~= zh*eh + zh*el + zl*eh, fp32 accumulate. fp16 split captures 22
// mantissa bits -> fast-path dist error ~5e-5 (fp32-accum bound), so the
// flag margin shrinks 5x vs bf16 and the fixup load drops ~5x.
// ---------------------------------------------------------------------------
__global__ __launch_bounds__(256, 1) void vq_argmin_mma(
    const float* __restrict__ z, const float* __restrict__ cb,
    float* __restrict__ idx_out, float* __restrict__ out_st,
    float* __restrict__ out_q)
{
    extern __shared__ __align__(16) char smem[];
    const uint32_t sbase = smem_u32(smem);
    const int tid  = threadIdx.x;
    const int wid  = tid >> 5;
    const int lane = tid & 31;
    const int rowBase = blockIdx.x * 128;

    const int warp_m = wid & 1;          // 0..1 (64 rows each)
    const int warp_n = wid >> 1;         // 0..3 (32 cols each)
    const int g = lane >> 2;             // row group within fragment
    const int q = lane & 3;              // col pair within fragment

    // esq -> smem
    #pragma unroll
    for (int i = 0; i < 4; i++)
        *(float*)(smem + SM_ESQ + (tid + i * 256) * 4) = g_esq[tid + i * 256];

    // Kick off chunk 0 copy immediately (overlaps the A conversion below)
    b_issue(sbase, 0, 0, tid);
    CP_COMMIT();

    // A: convert 128x256 fp32 -> fp16 hi/lo into padded smem.
    #pragma unroll 4
    for (int it = 0; it < 32; it++) {
        const int idx = it * 256 + tid;
        const int row = idx >> 6;
        const int c4  = idx & 63;
        const float4 v = *(const float4*)(z + (size_t)(rowBase + row) * D_ + c4 * 4);
        uint2 hh, ll;
        hh.x = pack_h2(v.x, v.y);
        hh.y = pack_h2(v.z, v.w);
        const __half2* hp0 = (const __half2*)&hh.x;
        const __half2* hp1 = (const __half2*)&hh.y;
        ll.x = pack_h2(__fsub_rn(v.x, __half2float(hp0->x)),
                       __fsub_rn(v.y, __half2float(hp0->y)));
        ll.y = pack_h2(__fsub_rn(v.z, __half2float(hp1->x)),
                       __fsub_rn(v.w, __half2float(hp1->y)));
        const uint32_t off = (uint32_t)row * (A_STRIDE * 2) + c4 * 8;
        *(uint2*)(smem + SM_AH + off) = hh;
        *(uint2*)(smem + SM_AL + off) = ll;
    }

    // ldmatrix per-lane base addresses.
    const int a_row_off = (lane & 7) + ((lane >> 3) & 1) * 8;
    const int a_k_off   = (lane >> 4) * 8;
    uint32_t aBaseH[4], aBaseL[4];
    #pragma unroll
    for (int mi = 0; mi < 4; mi++) {
        const uint32_t e = (uint32_t)(warp_m * 64 + mi * 16 + a_row_off) * A_STRIDE
                         + a_k_off;
        aBaseH[mi] = sbase + SM_AH + e * 2;
        aBaseL[mi] = sbase + SM_AL + e * 2;
    }
    const int b_n_off = (lane & 7) + (lane >> 4) * 8;
    const int b_k_off = ((lane >> 3) & 1) * 8;
    uint32_t bBase[2];                   // stage-0 hi; lo = +B_HALF, stage1 = +B_BUFSZ
    #pragma unroll
    for (int nj = 0; nj < 2; nj++) {
        const uint32_t e = (uint32_t)(warp_n * 32 + nj * 16 + b_n_off) * B_STRIDE
                         + b_k_off;
        bBase[nj] = sbase + SM_B + e * 2;
    }

    float bestv[4][2], secondv[4][2];
    int   besti[4][2];
    #pragma unroll
    for (int mi = 0; mi < 4; mi++)
        #pragma unroll
        for (int h = 0; h < 2; h++) {
            bestv[mi][h] = FLT_MAX; secondv[mi][h] = FLT_MAX; besti[mi][h] = 0;
        }

    float acc[4][4][4];
    int cur = 0;
    for (int c = 0; c < 32; c++) {
        const int kt = c >> 2, dk = c & 3;
        if (dk == 0) {
            #pragma unroll
            for (int mi = 0; mi < 4; mi++)
                #pragma unroll
                for (int n8 = 0; n8 < 4; n8++)
                    #pragma unroll
                    for (int u = 0; u < 4; u++) acc[mi][n8][u] = 0.f;
        }

        CP_WAIT0();          // chunk c landed in stage `cur`
        __syncthreads();     // visible to all warps; all warps done with stage cur^1
        if (c + 1 < 32) {    // start chunk c+1 into the other stage (overlaps MMAs)
            b_issue(sbase, c + 1, cur ^ 1, tid);
            CP_COMMIT();
        }

        const uint32_t curOff = (uint32_t)cur * B_BUFSZ;
        #pragma unroll
        for (int ks = 0; ks < 4; ks++) {
            const uint32_t akOff = (uint32_t)(dk * 64 + ks * 16) * 2;
            const uint32_t bkOff = (uint32_t)(ks * 16) * 2;
            uint32_t ah[4][4], al[4][4], bh[2][4], bl[2][4];
            #pragma unroll
            for (int mi = 0; mi < 4; mi++) {
                ldmx4(ah[mi], aBaseH[mi] + akOff);
                ldmx4(al[mi], aBaseL[mi] + akOff);
            }
            #pragma unroll
            for (int nj = 0; nj < 2; nj++) {
                ldmx4(bh[nj], bBase[nj] + curOff + bkOff);
                ldmx4(bl[nj], bBase[nj] + curOff + B_HALF + bkOff);
            }
            #pragma unroll
            for (int mi = 0; mi < 4; mi++)
                #pragma unroll
                for (int n8 = 0; n8 < 4; n8++) {
                    const int nj = n8 >> 1, s = (n8 & 1) * 2;
                    mma_f16(acc[mi][n8], ah[mi], bh[nj][s], bh[nj][s + 1]);
                    mma_f16(acc[mi][n8], ah[mi], bl[nj][s], bl[nj][s + 1]);
                    mma_f16(acc[mi][n8], al[mi], bh[nj][s], bh[nj][s + 1]);
                }
        }

        if (dk == 3) {
            // Fold this code tile into the running argmin (registers only).
            #pragma unroll
            for (int mi = 0; mi < 4; mi++)
                #pragma unroll
                for (int n8 = 0; n8 < 4; n8++) {
                    const int cbase = kt * 128 + warp_n * 32 + n8 * 8 + q * 2;
                    const float e0 = *(const float*)(smem + SM_ESQ + (cbase + 0) * 4);
                    const float e1 = *(const float*)(smem + SM_ESQ + (cbase + 1) * 4);
                    #pragma unroll
                    for (int h = 0; h < 2; h++) {
                        const float d0 = fmaf(-2.f, acc[mi][n8][h * 2 + 0], e0);
                        const float d1 = fmaf(-2.f, acc[mi][n8][h * 2 + 1], e1);
                        float* bv = &bestv[mi][h]; float* sv = &secondv[mi][h];
                        int*   bi = &besti[mi][h];
                        if (d0 < *bv) { *sv = *bv; *bv = d0; *bi = cbase; }
                        else            *sv = fminf(*sv, d0);
                        if (d1 < *bv) { *sv = *bv; *bv = d1; *bi = cbase + 1; }
                        else            *sv = fminf(*sv, d1);
                    }
                }
        }
        cur ^= 1;
    }

    // Quad merge (lanes 4g+0..3 hold the same rows, different cols)
    #pragma unroll
    for (int mi = 0; mi < 4; mi++)
        #pragma unroll
        for (int h = 0; h < 2; h++) {
            float bv = bestv[mi][h], s2 = secondv[mi][h];
            int   bi = besti[mi][h];
            #pragma unroll
            for (int off = 1; off <= 2; off <<= 1) {
                const float ob = __shfl_xor_sync(0xffffffffu, bv, off);
                const float os = __shfl_xor_sync(0xffffffffu, s2, off);
                const int   oi = __shfl_xor_sync(0xffffffffu, bi, off);
                const float bmax = fmaxf(bv, ob);
                const float smin = fminf(s2, os);
                if (ob < bv || (ob == bv && oi < bi)) { bv = ob; bi = oi; }
                s2 = fminf(smin, bmax);
            }
            bestv[mi][h] = bv; secondv[mi][h] = s2; besti[mi][h] = bi;
        }

    // Cross-n-warp merge through smem
    float* redb = (float*)(smem + SM_RED);            // [128][4]
    float* reds = (float*)(smem + SM_RED + 2048);     // [128][4]
    int*   redi = (int*)  (smem + SM_RED + 4096);     // [128][4]
    int*   ridx = (int*)  (smem + SM_RIDX);           // [128] final index
    __syncthreads();
    if (q == 0) {
        #pragma unroll
        for (int mi = 0; mi < 4; mi++)
            #pragma unroll
            for (int h = 0; h < 2; h++) {
                const int r = warp_m * 64 + mi * 16 + h * 8 + g;
                redb[r * 4 + warp_n] = bestv[mi][h];
                reds[r * 4 + warp_n] = secondv[mi][h];
                redi[r * 4 + warp_n] = besti[mi][h];
            }
    }
    __syncthreads();
    if (tid < 128) {
        float bv = redb[tid * 4], s2 = reds[tid * 4];
        int   bi = redi[tid * 4];
        #pragma unroll
        for (int t = 1; t < 4; t++) {
            const float ob = redb[tid * 4 + t];
            const float os = reds[tid * 4 + t];
            const int   oi = redi[tid * 4 + t];
            const float bmax = fmaxf(bv, ob);
            const float smin = fminf(s2, os);
            if (ob < bv || (ob == bv && oi < bi)) { bv = ob; bi = oi; }
            s2 = fminf(smin, bmax);
        }
        const int row = rowBase + tid;
        g_idx[row] = bi;
        ridx[tid] = bi;
        if (idx_out) idx_out[row] = (float)bi;
        if (s2 - bv < MARGIN_) {
            const int p = atomicAdd(&g_nflag, 1);
            g_flags[p] = row;
        }
    }
    __syncthreads();

    // Fused gather: 2 threads per row, 32 float4 each per output.
    if (out_st || out_q) {
        const int r = tid >> 1;
        const int h = tid & 1;
        const int ci = ridx[r];
        const float4* cr = (const float4*)(cb + (size_t)ci * D_) + h * 32;
        const float4* zr = (const float4*)(z + (size_t)(rowBase + r) * D_) + h * 32;
        float4* oq = out_q  ? (float4*)(out_q  + (size_t)(rowBase + r) * D_) + h * 32 : (float4*)0;
        float4* os = out_st ? (float4*)(out_st + (size_t)(rowBase + r) * D_) + h * 32 : (float4*)0;
        #pragma unroll 8
        for (int j = 0; j < 32; j++) {
            const float4 v = cr[j];
            if (oq) oq[j] = v;
            if (os) {
                const float4 zv = zr[j];
                float4 st;
                st.x = __fadd_rn(zv.x, __fsub_rn(v.x, zv.x));
                st.y = __fadd_rn(zv.y, __fsub_rn(v.y, zv.y));
                st.z = __fadd_rn(zv.z, __fsub_rn(v.z, zv.z));
                st.w = __fadd_rn(zv.w, __fsub_rn(v.w, zv.w));
                os[j] = st;
            }
        }
    }
}

// ---------------------------------------------------------------------------
// Kernel 3: tie-aware refinement (R15 architecture, validated): batched fp32
// scan -> candidate collection (window 2e-3 >> tie-T + 2x scan err) -> fp64
// exact for candidates only -> R10-validated tie rule (T = ulp_f32(best)+4e-5,
// lowest index). Rewrites idx / z_q / z_q_st for its rows.
// ---------------------------------------------------------------------------
#define FIX_BATCH 8
#define CAND_MAX  64

__global__ __launch_bounds__(256) void fixup_kernel(
    const float* __restrict__ z, const float* __restrict__ cb,
    float* __restrict__ idx_out, float* __restrict__ out_st,
    float* __restrict__ out_q)
{
    __shared__ __align__(16) float zrows[FIX_BATCH][D_];
    __shared__ double zsqs[FIX_BATCH];
    __shared__ float  wmin[FIX_BATCH][8];
    __shared__ float  rmin[FIX_BATCH];
    __shared__ int    rowids[FIX_BATCH];
    __shared__ int    cnt;
    __shared__ int    cand_row[CAND_MAX];
    __shared__ int    cand_code[CAND_MAX];
    __shared__ double cand_dist[CAND_MAX];
    __shared__ int    fidx[FIX_BATCH];

    const int tid  = threadIdx.x;
    const int wid  = tid >> 5;
    const int lane = tid & 31;
    const int n = g_nflag;

    for (int base = blockIdx.x * FIX_BATCH; base < n;
         base += gridDim.x * FIX_BATCH) {
        const int nb = min(FIX_BATCH, n - base);
        __syncthreads();                       // protect smem reuse across iters
        if (tid < nb) rowids[tid] = g_flags[base + tid];
        if (tid == 0) cnt = 0;
        __syncthreads();

        // Load the batch's z rows
        #pragma unroll
        for (int it = 0; it < FIX_BATCH; it++) {
            const int idx = it * 256 + tid;
            const int r = idx >> 8, d = idx & 255;
            if (r < nb) zrows[r][d] = z[(size_t)rowids[r] * D_ + d];
        }
        __syncthreads();

        // Exact z_sq per row (warp r handles row r)
        if (wid < nb) {
            double s = 0.0;
            #pragma unroll
            for (int j = 0; j < 8; j++) {
                const double x = (double)zrows[wid][lane + 32 * j];
                s = fma(x, x, s);
            }
            #pragma unroll
            for (int off = 16; off > 0; off >>= 1)
                s += __shfl_down_sync(0xffffffffu, s, off);
            if (lane == 0) zsqs[wid] = s;
        }

        // fp32 scan: each thread scores codes tid, tid+256, tid+512, tid+768
        // for all nb rows. dist32 = esq_f - 2*dot (z_sq row-constant).
        float dist32[4][FIX_BATCH];
        {
            float acc[4][FIX_BATCH];
            #pragma unroll
            for (int j = 0; j < 4; j++)
                #pragma unroll
                for (int r = 0; r < FIX_BATCH; r++) acc[j][r] = 0.f;

            for (int d4 = 0; d4 < 64; d4++) {
                float4 zf[FIX_BATCH];
                #pragma unroll
                for (int r = 0; r < FIX_BATCH; r++)
                    zf[r] = *(const float4*)&zrows[r][d4 * 4];
                #pragma unroll
                for (int j = 0; j < 4; j++) {
                    const float4 cv = *(const float4*)(cb +
                        (size_t)(j * 256 + tid) * D_ + d4 * 4);
                    #pragma unroll
                    for (int r = 0; r < FIX_BATCH; r++) {
                        acc[j][r] = fmaf(cv.x, zf[r].x, acc[j][r]);
                        acc[j][r] = fmaf(cv.y, zf[r].y, acc[j][r]);
                        acc[j][r] = fmaf(cv.z, zf[r].z, acc[j][r]);
                        acc[j][r] = fmaf(cv.w, zf[r].w, acc[j][r]);
                    }
                }
            }
            #pragma unroll
            for (int j = 0; j < 4; j++) {
                const float eq = g_esq[j * 256 + tid];
                #pragma unroll
                for (int r = 0; r < FIX_BATCH; r++)
                    dist32[j][r] = fmaf(-2.f, acc[j][r], eq);
            }
        }

        // Per-row min: thread-local over 4 codes -> warp shfl -> smem -> final
        #pragma unroll
        for (int r = 0; r < FIX_BATCH; r++) {
            float m = fminf(fminf(dist32[0][r], dist32[1][r]),
                            fminf(dist32[2][r], dist32[3][r]));
            #pragma unroll
            for (int off = 16; off > 0; off >>= 1)
                m = fminf(m, __shfl_down_sync(0xffffffffu, m, off));
            if (lane == 0) wmin[r][wid] = m;
        }
        __syncthreads();
        if (tid < nb) {
            float m = wmin[tid][0];
            #pragma unroll
            for (int t = 1; t < 8; t++) m = fminf(m, wmin[tid][t]);
            rmin[tid] = m;
        }
        __syncthreads();

        // Candidate collection (window 2e-3 >> T + 2*scan_err)
        #pragma unroll
        for (int j = 0; j < 4; j++)
            for (int r = 0; r < nb; r++)
                if (dist32[j][r] <= rmin[r] + 2e-3f) {
                    const int p = atomicAdd(&cnt, 1);
                    if (p < CAND_MAX) {
                        cand_row[p]  = r;
                        cand_code[p] = j * 256 + tid;
                    }
                }
        __syncthreads();
        const int nc = min(cnt, CAND_MAX);

        // Exact fp64 distance per candidate (one warp per candidate)
        for (int ci = wid; ci < nc; ci += 8) {
            const int r = cand_row[ci], c = cand_code[ci];
            const float* crow = cb + (size_t)c * D_;
            double dot = 0.0;
            #pragma unroll
            for (int j = 0; j < 8; j++) {
                const int d = lane + 32 * j;
                dot = fma((double)zrows[r][d], (double)crow[d], dot);
            }
            #pragma unroll
            for (int off = 16; off > 0; off >>= 1)
                dot += __shfl_down_sync(0xffffffffu, dot, off);
            if (lane == 0)
                cand_dist[ci] = zsqs[r] + (g_esqd[c] - 2.0 * dot);
        }
        __syncthreads();

        // Final decision per row: R10-validated tie rule.
        if (tid < nb) {
            double bestFull = 1e300;
            for (int i = 0; i < nc; i++)
                if (cand_row[i] == tid && cand_dist[i] < bestFull)
                    bestFull = cand_dist[i];
            int mi = 0x7fffffff;
            if (bestFull < 1e299) {
                double T;
                if (bestFull > 1.0) T = ldexp(1.0, ilogb(bestFull) - 23) + 4e-5;
                else                T = 5e-5;
                const double lim = bestFull + T;
                for (int i = 0; i < nc; i++)
                    if (cand_row[i] == tid && cand_dist[i] <= lim &&
                        cand_code[i] < mi)
                        mi = cand_code[i];
            }
            const int row = rowids[tid];
            if (mi == 0x7fffffff) mi = g_idx[row];   // overflow fallback (never)
            g_idx[row] = mi;
            if (idx_out) idx_out[row] = (float)mi;
            fidx[tid] = mi;
        }
        __syncthreads();

        // Rewrite z_q / z_q_st for the batch rows
        if (out_q || out_st) {
            #pragma unroll
            for (int it = 0; it < FIX_BATCH; it++) {
                const int idx = it * 256 + tid;
                const int r = idx >> 8, d = idx & 255;
                if (r < nb) {
                    const int row = rowids[r];
                    const float cv = cb[(size_t)fidx[r] * D_ + d];
                    if (out_q) out_q[(size_t)row * D_ + d] = cv;
                    if (out_st) {
                        const float zv = zrows[r][d];
                        out_st[(size_t)row * D_ + d] =
                            __fadd_rn(zv, __fsub_rn(cv, zv));
                    }
                }
            }
        }
    }
}

// ---------------------------------------------------------------------------
extern "C" void kernel_launch(void* const* d_in, const int* in_sizes, int n_in,
                              void* d_out, int out_size) {
    const float* z  = (const float*)d_in[0];   // z_e      [32,4096,256] f32
    const float* cb = (const float*)d_in[1];   // codebook [1024,256]    f32
    float* out = (float*)d_out;

    const long long bnd = (long long)NROWS * D_;   // 33,554,432
    float *p_st = nullptr, *p_q = nullptr, *p_idx = nullptr;
    const long long os = (long long)out_size;

    if (os >= 2 * bnd + NROWS) {                 // [z_q_st | z_q | indices]
        p_st = out; p_q = out + bnd; p_idx = out + 2 * bnd;
    } else if (os == 2 * bnd) {                  // [z_q_st | z_q]
        p_st = out; p_q = out + bnd;
    } else if (os == bnd + NROWS) {              // [z_q_st | indices]
        p_st = out; p_idx = out + bnd;
    } else if (os == bnd) {                      // [z_q_st]
        p_st = out;
    } else if (os == NROWS) {                    // [indices]
        p_idx = out;
    } else {                                     // fallback
        p_st = out;
    }

    // Opt-in to >48KB dynamic smem (idempotent; no allocation involved)
    cudaFuncSetAttribute(vq_argmin_mma, cudaFuncAttributeMaxDynamicSharedMemorySize,
                         SM_TOTAL);

    prep_kernel<<<1024, 256>>>(cb);
    esq_kernel<<<K_ / 8, 256>>>(cb);
    vq_argmin_mma<<<NROWS / 128, 256, SM_TOTAL>>>(z, cb, p_idx, p_st, p_q);
    fixup_kernel<<<512, 256>>>(z, cb, p_idx, p_st, p_q);
}

// round 17
// speedup vs baseline: 1.2618x; 1.2618x over previous
#include <cuda_runtime.h>
#include <cuda_fp16.h>
#include <cfloat>
#include <math.h>
#include <cstdint>

// Problem shape (fixed by the reference)
#define B_    32
#define N_    4096
#define D_    256
#define K_    1024
#define NROWS (B_ * N_)          // 131072 rows of z_e

// Fast path drops the zl*e term: dist error sigma ~4.6e-3 -> 0.04 = 8.7 sigma
#define MARGIN_ 0.04f

// ---------------------------------------------------------------------------
// SMEM layout (dynamic). Padded strides: row-to-row bank offset = 16B ->
// conflict-free ldmatrix. A is hi-only now; B gets a 3-stage pipeline.
// ---------------------------------------------------------------------------
#define A_STRIDE 264                       // 256 + 8 fp16
#define B_STRIDE 72                        // 64 + 8 fp16
#define SM_ESQ   0                         // 1024 f32 = 4 KB
#define SM_AH    4096                      // 128*264*2 = 67584
#define SM_B     (SM_AH + 67584)           // 3 stages x (hi 18432 + lo 18432)
#define B_HALF   18432                     // one precision, one stage
#define B_BUFSZ  36864                     // hi+lo per stage
#define SM_RED   (SM_B + 3 * B_BUFSZ)      // 6144: redb/reds/redi
#define SM_RIDX  (SM_RED + 6144)           // 512: final per-row index
#define SM_TOTAL (SM_RIDX + 512)           // 188928 B

// Scratch (static device globals -- no allocation allowed)
__device__ float  g_esq[K_];     // fp32 e_sq for the fast path
__device__ double g_esqd[K_];    // exact e_sq for the fixup
__device__ int    g_idx[NROWS];
__device__ int    g_nflag;
__device__ int    g_flags[NROWS];
// Pre-converted codebook (fp16 hi/lo), tiled EXACTLY like the smem B buffer:
// chunk c (kt=c>>2 codes kt*128..+128, dk=c&3 dims dk*64..+64)
__device__ __align__(16) __half g_cbh[32][128][B_STRIDE];
__device__ __align__(16) __half g_cbl[32][128][B_STRIDE];

__device__ __forceinline__ uint32_t smem_u32(const void* p) {
    uint32_t a;
    asm("{ .reg .u64 t; cvta.to.shared.u64 t, %1; cvt.u32.u64 %0, t; }"
        : "=r"(a) : "l"(p));
    return a;
}

__device__ __forceinline__ void ldmx4(uint32_t* r, uint32_t addr) {
    asm volatile("ldmatrix.sync.aligned.m8n8.x4.shared.b16 {%0,%1,%2,%3}, [%4];"
                 : "=r"(r[0]), "=r"(r[1]), "=r"(r[2]), "=r"(r[3]) : "r"(addr));
}

__device__ __forceinline__ void mma_f16(float* c, const uint32_t* a,
                                        uint32_t b0, uint32_t b1) {
    asm volatile(
        "mma.sync.aligned.m16n8k16.row.col.f32.f16.f16.f32 "
        "{%0,%1,%2,%3}, {%4,%5,%6,%7}, {%8,%9}, {%0,%1,%2,%3};"
        : "+f"(c[0]), "+f"(c[1]), "+f"(c[2]), "+f"(c[3])
        : "r"(a[0]), "r"(a[1]), "r"(a[2]), "r"(a[3]), "r"(b0), "r"(b1));
}

__device__ __forceinline__ uint32_t pack_h2(float x, float y) {
    const __half2 h = __floats2half2_rn(x, y);
    return *(const uint32_t*)&h;
}

__device__ __forceinline__ void cp16(uint32_t saddr, const void* gaddr) {
    asm volatile("cp.async.cg.shared.global [%0], [%1], 16;"
                 :: "r"(saddr), "l"(gaddr) : "memory");
}
#define CP_COMMIT() asm volatile("cp.async.commit_group;" ::: "memory")
#define CP_WAIT0()  asm volatile("cp.async.wait_group 0;" ::: "memory")
#define CP_WAIT1()  asm volatile("cp.async.wait_group 1;" ::: "memory")

// Issue async copy of chunk c into stage buffer `buf` (0..2). 2304 x 16B
// lines (hi 1152 + lo 1152), 9 per thread. Zero register residency.
__device__ __forceinline__ void b_issue(uint32_t sbase, int c, int buf, int tid) {
    const uint32_t dhi = sbase + SM_B + (uint32_t)buf * B_BUFSZ;
    const char* shi = (const char*)g_cbh[c];
    const char* slo = (const char*)g_cbl[c];
    #pragma unroll
    for (int it = 0; it < 9; it++) {
        const int line = it * 256 + tid;
        if (line < 1152) {
            cp16(dhi + line * 16, shi + line * 16);
        } else {
            const int l2 = line - 1152;
            cp16(dhi + B_HALF + l2 * 16, slo + l2 * 16);
        }
    }
}

// ---------------------------------------------------------------------------
// Kernel 0: pre-convert codebook into tiled fp16 hi/lo global buffers.
// hi = fp16(x); lo = fp16(x - hi): together ~22 mantissa bits of x.
// ---------------------------------------------------------------------------
__global__ void prep_kernel(const float* __restrict__ cb) {
    const int gid  = blockIdx.x * 256 + threadIdx.x;
    const int c    = gid >> 13;
    const int code = (gid & 8191) >> 6;
    const int d    = gid & 63;
    const int kt = c >> 2, dk = c & 3;
    const float v = cb[(size_t)(kt * 128 + code) * D_ + dk * 64 + d];
    const __half h = __float2half_rn(v);
    const __half l = __float2half_rn(__fsub_rn(v, __half2float(h)));
    g_cbh[c][code][d] = h;
    g_cbl[c][code][d] = l;
}

// ---------------------------------------------------------------------------
// Kernel 1: per-code squared norms, fp32 (fast path) + fp64 (exact, fixup).
// ---------------------------------------------------------------------------
__global__ void esq_kernel(const float* __restrict__ cb) {
    if (blockIdx.x == 0 && threadIdx.x == 0) g_nflag = 0;
    const int k    = blockIdx.x * 8 + (threadIdx.x >> 5);
    const int lane = threadIdx.x & 31;
    const float* row = cb + (size_t)k * D_;
    double sd = 0.0;
    #pragma unroll
    for (int j = 0; j < 8; j++) {
        const double x = (double)row[lane + 32 * j];
        sd = fma(x, x, sd);
    }
    #pragma unroll
    for (int off = 16; off > 0; off >>= 1)
        sd += __shfl_down_sync(0xffffffffu, sd, off);
    if (lane == 0) {
        g_esqd[k] = sd;
        g_esq[k]  = (float)sd;
    }
}

// ---------------------------------------------------------------------------
// Kernel 2: fp16 warp-MMA GEMM + fused argmin + fused gather.
// dot ~= zh*(eh + el): 2 MMAs per k-step (dropped zl*e, sigma ~4.6e-3,
// absorbed by MARGIN + fixup). A hi-only; 3-stage cp.async B pipeline
// (issue 2 chunks ahead, wait_group 1).
// ---------------------------------------------------------------------------
__global__ __launch_bounds__(256, 1) void vq_argmin_mma(
    const float* __restrict__ z, const float* __restrict__ cb,
    float* __restrict__ idx_out, float* __restrict__ out_st,
    float* __restrict__ out_q)
{
    extern __shared__ __align__(16) char smem[];
    const uint32_t sbase = smem_u32(smem);
    const int tid  = threadIdx.x;
    const int wid  = tid >> 5;
    const int lane = tid & 31;
    const int rowBase = blockIdx.x * 128;

    const int warp_m = wid & 1;          // 0..1 (64 rows each)
    const int warp_n = wid >> 1;         // 0..3 (32 cols each)
    const int g = lane >> 2;             // row group within fragment
    const int q = lane & 3;              // col pair within fragment

    // esq -> smem
    #pragma unroll
    for (int i = 0; i < 4; i++)
        *(float*)(smem + SM_ESQ + (tid + i * 256) * 4) = g_esq[tid + i * 256];

    // Kick off chunk 0 and 1 copies immediately (overlap the A conversion)
    b_issue(sbase, 0, 0, tid);
    CP_COMMIT();
    b_issue(sbase, 1, 1, tid);
    CP_COMMIT();

    // A: convert 128x256 fp32 -> fp16 hi into padded smem.
    #pragma unroll 4
    for (int it = 0; it < 32; it++) {
        const int idx = it * 256 + tid;
        const int row = idx >> 6;
        const int c4  = idx & 63;
        const float4 v = *(const float4*)(z + (size_t)(rowBase + row) * D_ + c4 * 4);
        uint2 hh;
        hh.x = pack_h2(v.x, v.y);
        hh.y = pack_h2(v.z, v.w);
        const uint32_t off = (uint32_t)row * (A_STRIDE * 2) + c4 * 8;
        *(uint2*)(smem + SM_AH + off) = hh;
    }

    // ldmatrix per-lane base addresses.
    const int a_row_off = (lane & 7) + ((lane >> 3) & 1) * 8;
    const int a_k_off   = (lane >> 4) * 8;
    uint32_t aBaseH[4];
    #pragma unroll
    for (int mi = 0; mi < 4; mi++) {
        const uint32_t e = (uint32_t)(warp_m * 64 + mi * 16 + a_row_off) * A_STRIDE
                         + a_k_off;
        aBaseH[mi] = sbase + SM_AH + e * 2;
    }
    const int b_n_off = (lane & 7) + (lane >> 4) * 8;
    const int b_k_off = ((lane >> 3) & 1) * 8;
    uint32_t bBase[2];                   // stage-0 hi; lo = +B_HALF, stage s = +s*B_BUFSZ
    #pragma unroll
    for (int nj = 0; nj < 2; nj++) {
        const uint32_t e = (uint32_t)(warp_n * 32 + nj * 16 + b_n_off) * B_STRIDE
                         + b_k_off;
        bBase[nj] = sbase + SM_B + e * 2;
    }

    float bestv[4][2], secondv[4][2];
    int   besti[4][2];
    #pragma unroll
    for (int mi = 0; mi < 4; mi++)
        #pragma unroll
        for (int h = 0; h < 2; h++) {
            bestv[mi][h] = FLT_MAX; secondv[mi][h] = FLT_MAX; besti[mi][h] = 0;
        }

    float acc[4][4][4];
    for (int c = 0; c < 32; c++) {
        const int kt = c >> 2, dk = c & 3;
        const int stage = c - (c / 3) * 3;           // c % 3
        if (dk == 0) {
            #pragma unroll
            for (int mi = 0; mi < 4; mi++)
                #pragma unroll
                for (int n8 = 0; n8 < 4; n8++)
                    #pragma unroll
                    for (int u = 0; u < 4; u++) acc[mi][n8][u] = 0.f;
        }

        // chunk c landed (allow chunk c+1 to stay in flight)
        if (c < 30) CP_WAIT1(); else CP_WAIT0();
        __syncthreads();     // data visible to all warps; stage (c+2)%3's old
                             // readers (chunk c-1 MMAs) are done
        if (c + 2 < 32) {    // issue chunk c+2, two ahead
            const int s2 = (c + 2) - ((c + 2) / 3) * 3;
            b_issue(sbase, c + 2, s2, tid);
            CP_COMMIT();
        }

        const uint32_t curOff = (uint32_t)stage * B_BUFSZ;
        #pragma unroll
        for (int ks = 0; ks < 4; ks++) {
            const uint32_t akOff = (uint32_t)(dk * 64 + ks * 16) * 2;
            const uint32_t bkOff = (uint32_t)(ks * 16) * 2;
            uint32_t ah[4][4], bh[2][4], bl[2][4];
            #pragma unroll
            for (int mi = 0; mi < 4; mi++)
                ldmx4(ah[mi], aBaseH[mi] + akOff);
            #pragma unroll
            for (int nj = 0; nj < 2; nj++) {
                ldmx4(bh[nj], bBase[nj] + curOff + bkOff);
                ldmx4(bl[nj], bBase[nj] + curOff + B_HALF + bkOff);
            }
            #pragma unroll
            for (int mi = 0; mi < 4; mi++)
                #pragma unroll
                for (int n8 = 0; n8 < 4; n8++) {
                    const int nj = n8 >> 1, s = (n8 & 1) * 2;
                    mma_f16(acc[mi][n8], ah[mi], bh[nj][s], bh[nj][s + 1]);
                    mma_f16(acc[mi][n8], ah[mi], bl[nj][s], bl[nj][s + 1]);
                }
        }

        if (dk == 3) {
            // Fold this code tile into the running argmin (registers only).
            #pragma unroll
            for (int mi = 0; mi < 4; mi++)
                #pragma unroll
                for (int n8 = 0; n8 < 4; n8++) {
                    const int cbase = kt * 128 + warp_n * 32 + n8 * 8 + q * 2;
                    const float e0 = *(const float*)(smem + SM_ESQ + (cbase + 0) * 4);
                    const float e1 = *(const float*)(smem + SM_ESQ + (cbase + 1) * 4);
                    #pragma unroll
                    for (int h = 0; h < 2; h++) {
                        const float d0 = fmaf(-2.f, acc[mi][n8][h * 2 + 0], e0);
                        const float d1 = fmaf(-2.f, acc[mi][n8][h * 2 + 1], e1);
                        float* bv = &bestv[mi][h]; float* sv = &secondv[mi][h];
                        int*   bi = &besti[mi][h];
                        if (d0 < *bv) { *sv = *bv; *bv = d0; *bi = cbase; }
                        else            *sv = fminf(*sv, d0);
                        if (d1 < *bv) { *sv = *bv; *bv = d1; *bi = cbase + 1; }
                        else            *sv = fminf(*sv, d1);
                    }
                }
        }
    }

    // Quad merge (lanes 4g+0..3 hold the same rows, different cols)
    #pragma unroll
    for (int mi = 0; mi < 4; mi++)
        #pragma unroll
        for (int h = 0; h < 2; h++) {
            float bv = bestv[mi][h], s2 = secondv[mi][h];
            int   bi = besti[mi][h];
            #pragma unroll
            for (int off = 1; off <= 2; off <<= 1) {
                const float ob = __shfl_xor_sync(0xffffffffu, bv, off);
                const float os = __shfl_xor_sync(0xffffffffu, s2, off);
                const int   oi = __shfl_xor_sync(0xffffffffu, bi, off);
                const float bmax = fmaxf(bv, ob);
                const float smin = fminf(s2, os);
                if (ob < bv || (ob == bv && oi < bi)) { bv = ob; bi = oi; }
                s2 = fminf(smin, bmax);
            }
            bestv[mi][h] = bv; secondv[mi][h] = s2; besti[mi][h] = bi;
        }

    // Cross-n-warp merge through smem
    float* redb = (float*)(smem + SM_RED);            // [128][4]
    float* reds = (float*)(smem + SM_RED + 2048);     // [128][4]
    int*   redi = (int*)  (smem + SM_RED + 4096);     // [128][4]
    int*   ridx = (int*)  (smem + SM_RIDX);           // [128] final index
    __syncthreads();
    if (q == 0) {
        #pragma unroll
        for (int mi = 0; mi < 4; mi++)
            #pragma unroll
            for (int h = 0; h < 2; h++) {
                const int r = warp_m * 64 + mi * 16 + h * 8 + g;
                redb[r * 4 + warp_n] = bestv[mi][h];
                reds[r * 4 + warp_n] = secondv[mi][h];
                redi[r * 4 + warp_n] = besti[mi][h];
            }
    }
    __syncthreads();
    if (tid < 128) {
        float bv = redb[tid * 4], s2 = reds[tid * 4];
        int   bi = redi[tid * 4];
        #pragma unroll
        for (int t = 1; t < 4; t++) {
            const float ob = redb[tid * 4 + t];
            const float os = reds[tid * 4 + t];
            const int   oi = redi[tid * 4 + t];
            const float bmax = fmaxf(bv, ob);
            const float smin = fminf(s2, os);
            if (ob < bv || (ob == bv && oi < bi)) { bv = ob; bi = oi; }
            s2 = fminf(smin, bmax);
        }
        const int row = rowBase + tid;
        g_idx[row] = bi;
        ridx[tid] = bi;
        if (idx_out) idx_out[row] = (float)bi;
        if (s2 - bv < MARGIN_) {
            const int p = atomicAdd(&g_nflag, 1);
            g_flags[p] = row;
        }
    }
    __syncthreads();

    // Fused gather: 2 threads per row, 32 float4 each per output.
    if (out_st || out_q) {
        const int r = tid >> 1;
        const int h = tid & 1;
        const int ci = ridx[r];
        const float4* cr = (const float4*)(cb + (size_t)ci * D_) + h * 32;
        const float4* zr = (const float4*)(z + (size_t)(rowBase + r) * D_) + h * 32;
        float4* oq = out_q  ? (float4*)(out_q  + (size_t)(rowBase + r) * D_) + h * 32 : (float4*)0;
        float4* os = out_st ? (float4*)(out_st + (size_t)(rowBase + r) * D_) + h * 32 : (float4*)0;
        #pragma unroll 8
        for (int j = 0; j < 32; j++) {
            const float4 v = cr[j];
            if (oq) oq[j] = v;
            if (os) {
                const float4 zv = zr[j];
                float4 st;
                st.x = __fadd_rn(zv.x, __fsub_rn(v.x, zv.x));
                st.y = __fadd_rn(zv.y, __fsub_rn(v.y, zv.y));
                st.z = __fadd_rn(zv.z, __fsub_rn(v.z, zv.z));
                st.w = __fadd_rn(zv.w, __fsub_rn(v.w, zv.w));
                os[j] = st;
            }
        }
    }
}

// ---------------------------------------------------------------------------
// Kernel 3: tie-aware refinement (R15 architecture, validated): batched fp32
// scan -> candidate collection (window 2e-3 >> tie-T + 2x scan err) -> fp64
// exact for candidates only -> R10-validated tie rule (T = ulp_f32(best)+4e-5,
// lowest index). Scan loop unrolled x4 to pipeline the L2 load chain (R16:
// 75us latency floor). Grid enlarged to 2048 for the bigger flag set.
// ---------------------------------------------------------------------------
#define FIX_BATCH 8
#define CAND_MAX  64

__global__ __launch_bounds__(256) void fixup_kernel(
    const float* __restrict__ z, const float* __restrict__ cb,
    float* __restrict__ idx_out, float* __restrict__ out_st,
    float* __restrict__ out_q)
{
    __shared__ __align__(16) float zrows[FIX_BATCH][D_];
    __shared__ double zsqs[FIX_BATCH];
    __shared__ float  wmin[FIX_BATCH][8];
    __shared__ float  rmin[FIX_BATCH];
    __shared__ int    rowids[FIX_BATCH];
    __shared__ int    cnt;
    __shared__ int    cand_row[CAND_MAX];
    __shared__ int    cand_code[CAND_MAX];
    __shared__ double cand_dist[CAND_MAX];
    __shared__ int    fidx[FIX_BATCH];

    const int tid  = threadIdx.x;
    const int wid  = tid >> 5;
    const int lane = tid & 31;
    const int n = g_nflag;

    for (int base = blockIdx.x * FIX_BATCH; base < n;
         base += gridDim.x * FIX_BATCH) {
        const int nb = min(FIX_BATCH, n - base);
        __syncthreads();                       // protect smem reuse across iters
        if (tid < nb) rowids[tid] = g_flags[base + tid];
        if (tid == 0) cnt = 0;
        __syncthreads();

        // Load the batch's z rows
        #pragma unroll
        for (int it = 0; it < FIX_BATCH; it++) {
            const int idx = it * 256 + tid;
            const int r = idx >> 8, d = idx & 255;
            if (r < nb) zrows[r][d] = z[(size_t)rowids[r] * D_ + d];
        }
        __syncthreads();

        // Exact z_sq per row (warp r handles row r)
        if (wid < nb) {
            double s = 0.0;
            #pragma unroll
            for (int j = 0; j < 8; j++) {
                const double x = (double)zrows[wid][lane + 32 * j];
                s = fma(x, x, s);
            }
            #pragma unroll
            for (int off = 16; off > 0; off >>= 1)
                s += __shfl_down_sync(0xffffffffu, s, off);
            if (lane == 0) zsqs[wid] = s;
        }

        // fp32 scan: each thread scores codes tid, tid+256, tid+512, tid+768
        // for all nb rows. dist32 = esq_f - 2*dot (z_sq row-constant).
        float dist32[4][FIX_BATCH];
        {
            float acc[4][FIX_BATCH];
            #pragma unroll
            for (int j = 0; j < 4; j++)
                #pragma unroll
                for (int r = 0; r < FIX_BATCH; r++) acc[j][r] = 0.f;

            #pragma unroll 4
            for (int d4 = 0; d4 < 64; d4++) {
                float4 zf[FIX_BATCH];
                #pragma unroll
                for (int r = 0; r < FIX_BATCH; r++)
                    zf[r] = *(const float4*)&zrows[r][d4 * 4];
                #pragma unroll
                for (int j = 0; j < 4; j++) {
                    const float4 cv = *(const float4*)(cb +
                        (size_t)(j * 256 + tid) * D_ + d4 * 4);
                    #pragma unroll
                    for (int r = 0; r < FIX_BATCH; r++) {
                        acc[j][r] = fmaf(cv.x, zf[r].x, acc[j][r]);
                        acc[j][r] = fmaf(cv.y, zf[r].y, acc[j][r]);
                        acc[j][r] = fmaf(cv.z, zf[r].z, acc[j][r]);
                        acc[j][r] = fmaf(cv.w, zf[r].w, acc[j][r]);
                    }
                }
            }
            #pragma unroll
            for (int j = 0; j < 4; j++) {
                const float eq = g_esq[j * 256 + tid];
                #pragma unroll
                for (int r = 0; r < FIX_BATCH; r++)
                    dist32[j][r] = fmaf(-2.f, acc[j][r], eq);
            }
        }

        // Per-row min: thread-local over 4 codes -> warp shfl -> smem -> final
        #pragma unroll
        for (int r = 0; r < FIX_BATCH; r++) {
            float m = fminf(fminf(dist32[0][r], dist32[1][r]),
                            fminf(dist32[2][r], dist32[3][r]));
            #pragma unroll
            for (int off = 16; off > 0; off >>= 1)
                m = fminf(m, __shfl_down_sync(0xffffffffu, m, off));
            if (lane == 0) wmin[r][wid] = m;
        }
        __syncthreads();
        if (tid < nb) {
            float m = wmin[tid][0];
            #pragma unroll
            for (int t = 1; t < 8; t++) m = fminf(m, wmin[tid][t]);
            rmin[tid] = m;
        }
        __syncthreads();

        // Candidate collection (window 2e-3 >> T + 2*scan_err)
        #pragma unroll
        for (int j = 0; j < 4; j++)
            for (int r = 0; r < nb; r++)
                if (dist32[j][r] <= rmin[r] + 2e-3f) {
                    const int p = atomicAdd(&cnt, 1);
                    if (p < CAND_MAX) {
                        cand_row[p]  = r;
                        cand_code[p] = j * 256 + tid;
                    }
                }
        __syncthreads();
        const int nc = min(cnt, CAND_MAX);

        // Exact fp64 distance per candidate (one warp per candidate)
        for (int ci = wid; ci < nc; ci += 8) {
            const int r = cand_row[ci], c = cand_code[ci];
            const float* crow = cb + (size_t)c * D_;
            double dot = 0.0;
            #pragma unroll
            for (int j = 0; j < 8; j++) {
                const int d = lane + 32 * j;
                dot = fma((double)zrows[r][d], (double)crow[d], dot);
            }
            #pragma unroll
            for (int off = 16; off > 0; off >>= 1)
                dot += __shfl_down_sync(0xffffffffu, dot, off);
            if (lane == 0)
                cand_dist[ci] = zsqs[r] + (g_esqd[c] - 2.0 * dot);
        }
        __syncthreads();

        // Final decision per row: R10-validated tie rule.
        if (tid < nb) {
            double bestFull = 1e300;
            for (int i = 0; i < nc; i++)
                if (cand_row[i] == tid && cand_dist[i] < bestFull)
                    bestFull = cand_dist[i];
            int mi = 0x7fffffff;
            if (bestFull < 1e299) {
                double T;
                if (bestFull > 1.0) T = ldexp(1.0, ilogb(bestFull) - 23) + 4e-5;
                else                T = 5e-5;
                const double lim = bestFull + T;
                for (int i = 0; i < nc; i++)
                    if (cand_row[i] == tid && cand_dist[i] <= lim &&
                        cand_code[i] < mi)
                        mi = cand_code[i];
            }
            const int row = rowids[tid];
            if (mi == 0x7fffffff) mi = g_idx[row];   // overflow fallback (never)
            g_idx[row] = mi;
            if (idx_out) idx_out[row] = (float)mi;
            fidx[tid] = mi;
        }
        __syncthreads();

        // Rewrite z_q / z_q_st for the batch rows
        if (out_q || out_st) {
            #pragma unroll
            for (int it = 0; it < FIX_BATCH; it++) {
                const int idx = it * 256 + tid;
                const int r = idx >> 8, d = idx & 255;
                if (r < nb) {
                    const int row = rowids[r];
                    const float cv = cb[(size_t)fidx[r] * D_ + d];
                    if (out_q) out_q[(size_t)row * D_ + d] = cv;
                    if (out_st) {
                        const float zv = zrows[r][d];
                        out_st[(size_t)row * D_ + d] =
                            __fadd_rn(zv, __fsub_rn(cv, zv));
                    }
                }
            }
        }
    }
}

// ---------------------------------------------------------------------------
extern "C" void kernel_launch(void* const* d_in, const int* in_sizes, int n_in,
                              void* d_out, int out_size) {
    const float* z  = (const float*)d_in[0];   // z_e      [32,4096,256] f32
    const float* cb = (const float*)d_in[1];   // codebook [1024,256]    f32
    float* out = (float*)d_out;

    const long long bnd = (long long)NROWS * D_;   // 33,554,432
    float *p_st = nullptr, *p_q = nullptr, *p_idx = nullptr;
    const long long os = (long long)out_size;

    if (os >= 2 * bnd + NROWS) {                 // [z_q_st | z_q | indices]
        p_st = out; p_q = out + bnd; p_idx = out + 2 * bnd;
    } else if (os == 2 * bnd) {                  // [z_q_st | z_q]
        p_st = out; p_q = out + bnd;
    } else if (os == bnd + NROWS) {              // [z_q_st | indices]
        p_st = out; p_idx = out + bnd;
    } else if (os == bnd) {                      // [z_q_st]
        p_st = out;
    } else if (os == NROWS) {                    // [indices]
        p_idx = out;
    } else {                                     // fallback
        p_st = out;
    }

    // Opt-in to >48KB dynamic smem (idempotent; no allocation involved)
    cudaFuncSetAttribute(vq_argmin_mma, cudaFuncAttributeMaxDynamicSharedMemorySize,
                         SM_TOTAL);

    prep_kernel<<<1024, 256>>>(cb);
    esq_kernel<<<K_ / 8, 256>>>(cb);
    vq_argmin_mma<<<NROWS / 128, 256, SM_TOTAL>>>(z, cb, p_idx, p_st, p_q);
    fixup_kernel<<<2048, 256>>>(z, cb, p_idx, p_st, p_q);
}